// round 17
// baseline (speedup 1.0000x reference)
#include <cuda_runtime.h>
#include <cuda_fp16.h>

#define THREADS 256
#define WIN     9
#define EDGE    4
#define QPW     32         // queries per warp (phase-1 fully parallel)
#define VT_CAP  (2048 * 64)

__device__ __half g_vh[VT_CAP];   // fp16 copy of vector_table (rebuilt every launch)

// ---------- pre-pass: fp32 -> fp16 table conversion (8 elems/thread, vectorized) ----------
__global__ __launch_bounds__(256)
void k_cvt(const float* __restrict__ v, int n8)
{
    int i = blockIdx.x * blockDim.x + threadIdx.x;   // one per 8 elements
    if (i >= n8) return;
    const float4* src = (const float4*)v + 2 * (size_t)i;
    float4 f0 = __ldg(src);
    float4 f1 = __ldg(src + 1);
    __half2 h0 = __floats2half2_rn(f0.x, f0.y);
    __half2 h1 = __floats2half2_rn(f0.z, f0.w);
    __half2 h2 = __floats2half2_rn(f1.x, f1.y);
    __half2 h3 = __floats2half2_rn(f1.z, f1.w);
    uint4 o;
    o.x = *(unsigned*)&h0; o.y = *(unsigned*)&h1;
    o.z = *(unsigned*)&h2; o.w = *(unsigned*)&h3;
    ((uint4*)g_vh)[i] = o;
}

// packed f32x2 helpers (sm_103a FFMA2 — PTX-only, ptxas won't auto-fuse)
__device__ __forceinline__ unsigned long long pack2(float lo, float hi) {
    unsigned long long r;
    asm("mov.b64 %0, {%1, %2};" : "=l"(r) : "f"(lo), "f"(hi));
    return r;
}
__device__ __forceinline__ void ffma2(unsigned long long& acc,
                                      unsigned long long a, unsigned long long b) {
    asm("fma.rn.f32x2 %0, %1, %2, %0;" : "+l"(acc) : "l"(a), "l"(b));
}
__device__ __forceinline__ float2 unpack2(unsigned long long v) {
    float2 f;
    asm("mov.b64 {%0, %1}, %2;" : "=f"(f.x), "=f"(f.y) : "l"(v));
    return f;
}

__global__ __launch_bounds__(THREADS)
void hwnet_kernel(const float* __restrict__ x,
                  const float* __restrict__ etab,
                  const float* __restrict__ tctab,
                  float* __restrict__ out,
                  int B, int T)
{
    const int tid  = threadIdx.x;
    const int warp = tid >> 5;
    const int lane = tid & 31;
    const int qwarp = (blockIdx.x * (THREADS / 32) + warp) * QPW;

    // ---- Phase 1 (ALL 32 lanes): each lane computes idx + softmax for its own query.
    // Coalesced x load; full-warp MUFU/FMA utilization (~2 issues/query vs 15 before).
    float wv[WIN];
    int base;
    {
        const int q = qwarp + lane;
        const float xv = x[min(q, B - 1)];

        const float e0 = __ldg(&etab[0]);
        const float eN = __ldg(&etab[T - 1]);
        const float inv_step = (float)(T - 1) / (eN - e0);
        int i0 = (int)floorf((xv - e0) * inv_step);

        int idx = 0;
        float best = 3.4e38f;
        #pragma unroll
        for (int k = 0; k < 4; k++) {
            int cc = min(max(i0 - 1 + k, 0), T - 1);
            float d = xv - __ldg(&etab[cc]);
            d *= d;
            if (d < best) { best = d; idx = cc; }   // strict '<' == argmin first-occurrence
        }

        const float tc = __ldg(&tctab[idx]);        // UNCLIPPED idx (matches reference)
        base = min(max(idx, EDGE), T - 1 - EDGE) - EDGE;

        float m = -3.4e38f;
        #pragma unroll
        for (int j = 0; j < WIN; j++) {
            float e = __ldg(&etab[base + j]);
            float d = xv - e;
            float l = -(d * d) * tc;
            wv[j] = l;
            m = fmaxf(m, l);
        }
        float sum = 0.0f;
        #pragma unroll
        for (int j = 0; j < WIN; j++) {
            float p = __expf(wv[j] - m);
            wv[j] = p;
            sum += p;
        }
        const float inv = __frcp_rn(sum);
        #pragma unroll
        for (int j = 0; j < WIN; j++) wv[j] *= inv;
    }

    // ---- Phase 2: 8 rounds; round t serves queries qwarp+4t..4t+3 (8 lanes each)
    const int qsel = lane >> 3;       // 0..3: which query of the current group
    const int sub  = lane & 7;        // 0..7: which 16B (8-half) chunk of D=64
    const uint4* vt = (const uint4*)g_vh;            // 8 uint4 per 64-half row

    #pragma unroll 1
    for (int t = 0; t < QPW / 4; t++) {
        const int src = t * 4 + qsel;                // lane holding this query's weights
        const int bb  = __shfl_sync(0xffffffffu, base, src);
        const int gq  = qwarp + src;

        unsigned long long acc0 = pack2(0.f, 0.f);
        unsigned long long acc1 = acc0, acc2 = acc0, acc3 = acc0;

        #pragma unroll
        for (int j = 0; j < WIN; j++) {
            const float wj = __shfl_sync(0xffffffffu, wv[j], src);
            uint4 h = __ldg(vt + (size_t)(bb + j) * 8 + sub);
            unsigned long long w2 = pack2(wj, wj);
            float2 f0 = __half22float2(*(__half2*)&h.x);
            float2 f1 = __half22float2(*(__half2*)&h.y);
            float2 f2 = __half22float2(*(__half2*)&h.z);
            float2 f3 = __half22float2(*(__half2*)&h.w);
            ffma2(acc0, pack2(f0.x, f0.y), w2);
            ffma2(acc1, pack2(f1.x, f1.y), w2);
            ffma2(acc2, pack2(f2.x, f2.y), w2);
            ffma2(acc3, pack2(f3.x, f3.y), w2);
        }

        float2 r0 = unpack2(acc0), r1 = unpack2(acc1);
        float2 r2 = unpack2(acc2), r3 = unpack2(acc3);

        if (gq < B) {
            float4* o = (float4*)(out + (size_t)gq * 64 + sub * 8);
            __stcs(o,     make_float4(r0.x, r0.y, r1.x, r1.y));
            __stcs(o + 1, make_float4(r2.x, r2.y, r3.x, r3.y));
        }
    }
}

extern "C" void kernel_launch(void* const* d_in, const int* in_sizes, int n_in,
                              void* d_out, int out_size)
{
    const float* x     = (const float*)d_in[0];   // [B,1]
    const float* etab  = (const float*)d_in[1];   // [T,1]
    const float* tctab = (const float*)d_in[2];   // [T,1]
    const float* vtab  = (const float*)d_in[3];   // [T,D]
    float* out = (float*)d_out;

    const int B  = in_sizes[0];                   // 131072
    const int T  = in_sizes[1];                   // 2048
    const int nv = min(in_sizes[3], VT_CAP);      // 131072 table elements
    const int n8 = nv / 8;                        // 16384 vectorized units

    k_cvt<<<(n8 + 255) / 256, 256>>>(vtab, n8);

    const int qpb    = (THREADS / 32) * QPW;      // 256 queries per block
    const int blocks = (B + qpb - 1) / qpb;       // 512
    hwnet_kernel<<<blocks, THREADS>>>(x, etab, tctab, out, B, T);
}